// round 2
// baseline (speedup 1.0000x reference)
#include <cuda_runtime.h>
#include <math.h>

// B=256 T=20 NOBJ=5 D=2048 P=1000 IN=2018 H=512

// ------------------------- device scratch -------------------------
__device__ float g_MH [2048*512];
__device__ float g_MO [2048*512];
__device__ float g_CHv[512];
__device__ float g_COv[512];
__device__ float g_Y  [30720*512];
__device__ float g_G1 [30720*512];
__device__ float g_Z  [30720*512];
__device__ float g_SG [30720*512];
__device__ float g_HN [5120*512];
__device__ float g_ON [25600*1024];
__device__ float g_XPH[5120*512];
__device__ float g_HR0[5120*512];
__device__ float g_HR1[5120*512];
__device__ float g_XPO[25600*1024];
__device__ float g_OR0[25600*1024];
__device__ float g_OR1[25600*1024];
__device__ float g_A1H[5120*512];
__device__ float g_A1O[25600*512];
__device__ int   g_off[257];

// ---------------------------------------------------------------------------
// Generic tiled fp32 GEMM.
//  amode: 0 A[m*lda+k], 1 human-RF, 2 obj-RF, 3 A[k*lda+m], 4 RNN hprev
//  bmode: 0 B[k*ldb+n], 1 B[n*ldb+k]   (amode==4: Bp += d*Hd*Hd)
//  cmode: 0 crow=m, 1 crow=m*6, 2 obj row map
//  epi:   0 none, 1 bias+relu, 2 rnn step tanh(acc+XP+bih+bhh)
// ---------------------------------------------------------------------------
struct GemmP {
  const float* A; const float* B; float* C;
  int M, N, K;
  int amode, lda, bmode, ldb, cmode, ldc;
  int epi; const float* bias1;
  int s, Tn, Hd;
  const float* XP; const float* bih; const float* bhh;
};

template<int BM,int BN,int BK,int TM,int TN>
__global__ __launch_bounds__(256) void gemm_k(GemmP p)
{
  const int d = blockIdx.z;
  int t = 0, tprev = 0;
  if (p.amode == 4) { t = d ? (p.Tn - 1 - p.s) : p.s; tprev = d ? (t + 1) : (t - 1); }
  const int m0 = blockIdx.y * BM;
  const int n0 = blockIdx.x * BN;

  __shared__ float As[BK][BM+4];
  __shared__ float Bs[BK][BN+4];
  float acc[TM][TN];
#pragma unroll
  for (int i=0;i<TM;i++)
#pragma unroll
    for (int j=0;j<TN;j++) acc[i][j]=0.f;

  const float* Bp = p.B + ((p.amode==4) ? (size_t)d * p.Hd * p.Hd : (size_t)0);
  const int tid = threadIdx.x;
  const int tm0 = (tid >> 4) * TM;
  const int tn0 = (tid & 15) * TN;

  for (int k0 = 0; k0 < p.K; k0 += BK) {
    for (int idx = tid; idx < BM*BK; idx += 256) {
      int kl, ml;
      if (p.amode == 3) { kl = idx / BM; ml = idx - kl*BM; }
      else              { ml = idx / BK; kl = idx - ml*BK; }
      int m = m0 + ml, k = k0 + kl;
      float v = 0.f;
      if (m < p.M && k < p.K) {
        if (p.amode == 0)      v = p.A[(size_t)m * p.lda + k];
        else if (p.amode == 1) { int b = m/20, tt = m - b*20;
                                 v = p.A[((size_t)(b*120 + tt))*2048 + k]; }
        else if (p.amode == 2) { int b = m/100, rm = m - b*100;
                                 int u = 1 + rm/20, tt = rm - (u-1)*20;
                                 v = p.A[((size_t)(b*120 + u*20 + tt))*2048 + k]; }
        else if (p.amode == 3) v = p.A[(size_t)k * p.lda + m];
        else                   v = p.A[((size_t)m * p.Tn + tprev)*(size_t)(2*p.Hd)
                                       + (size_t)d*p.Hd + k];
      }
      As[kl][ml] = v;
    }
    for (int idx = tid; idx < BK*BN; idx += 256) {
      int kl, nl;
      if (p.bmode == 1) { nl = idx / BK; kl = idx - nl*BK; }
      else              { kl = idx / BN; nl = idx - kl*BN; }
      int k = k0 + kl, n = n0 + nl;
      float v = 0.f;
      if (k < p.K && n < p.N)
        v = (p.bmode==1) ? Bp[(size_t)n * p.ldb + k] : Bp[(size_t)k * p.ldb + n];
      Bs[kl][nl] = v;
    }
    __syncthreads();
#pragma unroll
    for (int kk=0; kk<BK; kk++) {
      float a[TM], b[TN];
#pragma unroll
      for (int i=0;i<TM;i++) a[i] = As[kk][tm0+i];
#pragma unroll
      for (int j=0;j<TN;j++) b[j] = Bs[kk][tn0+j];
#pragma unroll
      for (int i=0;i<TM;i++)
#pragma unroll
        for (int j=0;j<TN;j++) acc[i][j] = fmaf(a[i], b[j], acc[i][j]);
    }
    __syncthreads();
  }

#pragma unroll
  for (int i=0;i<TM;i++) {
    int m = m0 + tm0 + i;
    if (m >= p.M) continue;
    size_t crow = 0;
    if (p.cmode == 0) crow = (size_t)m;
    else if (p.cmode == 1) crow = (size_t)m * 6;
    else if (p.cmode == 2) { int b = m/100, rm = m - b*100;
                             int u = 1 + rm/20, tt = rm - (u-1)*20;
                             crow = ((size_t)(b*20+tt))*6 + u; }
#pragma unroll
    for (int j=0;j<TN;j++) {
      int n = n0 + tn0 + j;
      if (n >= p.N) continue;
      float v = acc[i][j];
      if (p.epi == 2) {
        size_t o = ((size_t)m * p.Tn + t)*(size_t)(2*p.Hd) + (size_t)d*p.Hd + n;
        v += p.XP[o] + p.bih[d*p.Hd + n] + p.bhh[d*p.Hd + n];
        p.C[o] = tanhf(v);
      } else {
        if (p.epi == 1) { v += p.bias1[n]; v = fmaxf(v, 0.f); }
        p.C[crow * (size_t)p.ldc + n] = v;
      }
    }
  }
}

// CH[h] = sum_p bph[p]*Wg1[4+p][h]; CO with bpo/Wg1[1004:2004]
__global__ void chco_k(const float* bph, const float* bpo, const float* Wg1,
                       float* CHv, float* COv)
{
  __shared__ float sa[256], sc[256];
  int hl = threadIdx.x & 31, sl = threadIdx.x >> 5;
  int h = blockIdx.x*32 + hl;
  float a=0.f, c=0.f;
  for (int q=0; q<125; q++){
    int pp = sl*125 + q;
    a += bph[pp]*Wg1[(size_t)(4+pp)*512 + h];
    c += bpo[pp]*Wg1[(size_t)(1004+pp)*512 + h];
  }
  sa[threadIdx.x]=a; sc[threadIdx.x]=c;
  __syncthreads();
  if (sl==0){
    for (int s2=1;s2<8;s2++){ a+=sa[s2*32+hl]; c+=sc[s2*32+hl]; }
    CHv[h]=a; COv[h]=c;
  }
}

// mix1: slivers + A_HAT mix + bg1 + relu
__global__ void mix1_k(const float* __restrict__ Y, const float* __restrict__ Wg1,
                       const float* __restrict__ bg1, const float* __restrict__ bbox,
                       const float* __restrict__ oh, const float* __restrict__ CHv,
                       const float* __restrict__ COv, float* __restrict__ G1)
{
  int bt = blockIdx.x; int b = bt/20, t = bt - b*20;
  __shared__ float sb[24], so[50];
  int tid = threadIdx.x;
  if (tid < 24) sb[tid] = bbox[((size_t)(b*6 + (tid>>2))*20 + t)*4 + (tid&3)];
  if (tid >= 32 && tid < 82) {
    int q = tid-32;
    so[q] = oh[((size_t)(b*5 + q/10)*20 + t)*10 + (q - (q/10)*10)];
  }
  __syncthreads();
  int h = tid;
  size_t base = (size_t)bt * 6 * 512;
  float y0 = Y[base + h] + CHv[h];
#pragma unroll
  for (int i=0;i<4;i++) y0 += sb[i]*Wg1[(size_t)i*512 + h];
  float ys = 0.f, yu[5];
#pragma unroll
  for (int u=1; u<=5; u++){
    float v = Y[base + (size_t)u*512 + h] + COv[h];
#pragma unroll
    for (int i=0;i<4;i++) v += sb[u*4+i]*Wg1[(size_t)(2004+i)*512 + h];
#pragma unroll
    for (int j=0;j<10;j++) v += so[(u-1)*10+j]*Wg1[(size_t)(2008+j)*512 + h];
    yu[u-1]=v; ys += v;
  }
  const float R6 = 1.f/6.f, R12 = 0.28867513459481287f;
  float bg = bg1[h];
  G1[base + h] = fmaxf(R6*y0 + R12*ys + bg, 0.f);
#pragma unroll
  for (int u=1;u<=5;u++)
    G1[base + (size_t)u*512 + h] = fmaxf(R12*y0 + 0.5f*yu[u-1] + bg, 0.f);
}

// mix2: A_HAT mix + bg2 + relu -> SG; extract human node -> HN
__global__ void mix2_k(const float* __restrict__ Z, const float* __restrict__ bg2,
                       float* __restrict__ SG, float* __restrict__ HN)
{
  int bt = blockIdx.x;
  int h = threadIdx.x;
  size_t base = (size_t)bt*6*512;
  float z0 = Z[base+h];
  float zs=0.f, zu[5];
#pragma unroll
  for (int u=1;u<=5;u++){ float v = Z[base+(size_t)u*512+h]; zu[u-1]=v; zs+=v; }
  const float R6 = 1.f/6.f, R12 = 0.28867513459481287f;
  float bg = bg2[h];
  float g0 = fmaxf(R6*z0 + R12*zs + bg, 0.f);
  SG[base+h]=g0;
  HN[(size_t)bt*512+h]=g0;
#pragma unroll
  for (int u=1;u<=5;u++)
    SG[base+(size_t)u*512+h] = fmaxf(R12*z0 + 0.5f*zu[u-1] + bg, 0.f);
}

__global__ void prefix_k(const int* num, int* off){
  if (threadIdx.x==0){
    int a=0;
    for (int b=0;b<256;b++){ off[b]=a; a+=num[b]; }
    off[256]=a;
  }
}

__global__ void gather_k(const float* __restrict__ SG, const int* __restrict__ num,
                         const int* __restrict__ off, float* __restrict__ ON)
{
  int bk = blockIdx.x; int b = bk/5, k = bk - b*5;
  if (k >= num[b]) return;
  int t = blockIdx.y;
  int r = off[b] + k;
  size_t ob  = ((size_t)r*20 + t)*1024;
  size_t sgb = ((size_t)(b*20+t))*6*512;
  int h = threadIdx.x;
  ON[ob + h]       = SG[sgb + h];
  ON[ob + 512 + h] = SG[sgb + (size_t)(k+1)*512 + h];
}

// out[r,i] = (sum_t A1[r,t,:]) . W2[i,:] + 20*b2[i]
__global__ void head_k(const float* __restrict__ A1, const float* __restrict__ W2,
                       const float* __restrict__ b2, float* __restrict__ out, int nout)
{
  int r = blockIdx.x;
  __shared__ float cs[512];
  __shared__ float red[256];
  int tid = threadIdx.x;
  for (int j = tid; j < 512; j += 256){
    float s = 0.f;
    for (int t=0;t<20;t++) s += A1[((size_t)r*20 + t)*512 + j];
    cs[j] = s;
  }
  __syncthreads();
  for (int i=0;i<nout;i++){
    float v = cs[tid]*W2[(size_t)i*512+tid] + cs[tid+256]*W2[(size_t)i*512+tid+256];
    red[tid]=v; __syncthreads();
    for (int st=128; st>0; st>>=1){ if (tid<st) red[tid]+=red[tid+st]; __syncthreads(); }
    if (tid==0) out[(size_t)r*nout + i] = red[0] + 20.f*b2[i];
    __syncthreads();
  }
}

// ------------------------------- host side ---------------------------------
static inline void launch_big(const GemmP& p, int z = 1){
  dim3 g((unsigned)((p.N+63)/64), (unsigned)((p.M+127)/128), (unsigned)z);
  gemm_k<128,64,16,8,4><<<g,256>>>(p);
}
static inline void launch_sm(const GemmP& p, int z = 1){
  dim3 g((unsigned)((p.N+31)/32), (unsigned)((p.M+63)/64), (unsigned)z);
  gemm_k<64,32,16,4,2><<<g,256>>>(p);
}

extern "C" void kernel_launch(void* const* d_in, const int* in_sizes, int n_in,
                              void* d_out, int out_size)
{
  const float* one_hot = (const float*)d_in[0];
  const float* bbox    = (const float*)d_in[1];
  const int*   numobj  = (const int*)  d_in[2];
  const float* rf      = (const float*)d_in[3];
  const float* Wph  = (const float*)d_in[4];
  const float* bph  = (const float*)d_in[5];
  const float* Wpo  = (const float*)d_in[6];
  const float* bpo  = (const float*)d_in[7];
  const float* Wg1  = (const float*)d_in[8];
  const float* bg1  = (const float*)d_in[9];
  const float* Wg2  = (const float*)d_in[10];
  const float* bg2  = (const float*)d_in[11];
  const float* sWih = (const float*)d_in[12];
  const float* sWhh = (const float*)d_in[13];
  const float* sbih = (const float*)d_in[14];
  const float* sbhh = (const float*)d_in[15];
  const float* aWih = (const float*)d_in[16];
  const float* aWhh = (const float*)d_in[17];
  const float* abih = (const float*)d_in[18];
  const float* abhh = (const float*)d_in[19];
  const float* chW1 = (const float*)d_in[20];
  const float* chb1 = (const float*)d_in[21];
  const float* chW2 = (const float*)d_in[22];
  const float* chb2 = (const float*)d_in[23];
  const float* coW1 = (const float*)d_in[24];
  const float* cob1 = (const float*)d_in[25];
  const float* coW2 = (const float*)d_in[26];
  const float* cob2 = (const float*)d_in[27];
  float* out = (float*)d_out;

  int Ntot = (out_size - 2560) / 12;
  if (Ntot < 0) Ntot = 0; if (Ntot > 1280) Ntot = 1280;

  float *MH,*MO,*CHv,*COv,*Y,*G1,*Z,*SG,*HN,*ON,*XPH,*HR0,*HR1,*XPO,*OR0,*OR1,*A1H,*A1O;
  int *off;
  cudaGetSymbolAddress((void**)&MH,  g_MH);
  cudaGetSymbolAddress((void**)&MO,  g_MO);
  cudaGetSymbolAddress((void**)&CHv, g_CHv);
  cudaGetSymbolAddress((void**)&COv, g_COv);
  cudaGetSymbolAddress((void**)&Y,   g_Y);
  cudaGetSymbolAddress((void**)&G1,  g_G1);
  cudaGetSymbolAddress((void**)&Z,   g_Z);
  cudaGetSymbolAddress((void**)&SG,  g_SG);
  cudaGetSymbolAddress((void**)&HN,  g_HN);
  cudaGetSymbolAddress((void**)&ON,  g_ON);
  cudaGetSymbolAddress((void**)&XPH, g_XPH);
  cudaGetSymbolAddress((void**)&HR0, g_HR0);
  cudaGetSymbolAddress((void**)&HR1, g_HR1);
  cudaGetSymbolAddress((void**)&XPO, g_XPO);
  cudaGetSymbolAddress((void**)&OR0, g_OR0);
  cudaGetSymbolAddress((void**)&OR1, g_OR1);
  cudaGetSymbolAddress((void**)&A1H, g_A1H);
  cudaGetSymbolAddress((void**)&A1O, g_A1O);
  cudaGetSymbolAddress((void**)&off, g_off);

  // MH = Wph^T @ Wg1[4:1004] ; MO = Wpo^T @ Wg1[1004:2004]
  { GemmP p{}; p.A=Wph; p.amode=3; p.lda=2048; p.B=Wg1+4*512; p.bmode=0; p.ldb=512;
    p.C=MH; p.cmode=0; p.ldc=512; p.M=2048; p.N=512; p.K=1000; launch_big(p); }
  { GemmP p{}; p.A=Wpo; p.amode=3; p.lda=2048; p.B=Wg1+1004*512; p.bmode=0; p.ldb=512;
    p.C=MO; p.cmode=0; p.ldc=512; p.M=2048; p.N=512; p.K=1000; launch_big(p); }
  chco_k<<<16,256>>>(bph, bpo, Wg1, CHv, COv);

  // Y = rf @ M  (written [b,t,u,512])
  { GemmP p{}; p.A=rf; p.amode=1; p.B=MH; p.bmode=0; p.ldb=512;
    p.C=Y; p.cmode=1; p.ldc=512; p.M=5120; p.N=512; p.K=2048; launch_big(p); }
  { GemmP p{}; p.A=rf; p.amode=2; p.B=MO; p.bmode=0; p.ldb=512;
    p.C=Y; p.cmode=2; p.ldc=512; p.M=25600; p.N=512; p.K=2048; launch_big(p); }
  mix1_k<<<5120,512>>>(Y, Wg1, bg1, bbox, one_hot, CHv, COv, G1);

  // Z = G1 @ Wg2 -> mix2 -> SG, HN
  { GemmP p{}; p.A=G1; p.amode=0; p.lda=512; p.B=Wg2; p.bmode=0; p.ldb=512;
    p.C=Z; p.cmode=0; p.ldc=512; p.M=30720; p.N=512; p.K=512; launch_big(p); }
  mix2_k<<<5120,512>>>(Z, bg2, SG, HN);

  prefix_k<<<1,32>>>(numobj, off);
  gather_k<<<dim3(1280,20),512>>>(SG, numobj, off, ON);

  // human bidir RNN (hidden 256/dir)
  for (int l=0;l<2;l++){
    GemmP p{}; p.A = (l==0)?HN:HR0; p.amode=0; p.lda=512;
    p.B = sWih + (size_t)l*2*256*512; p.bmode=1; p.ldb=512;
    p.C = XPH; p.cmode=0; p.ldc=512; p.M=5120; p.N=512; p.K=512;
    launch_big(p);
    float* HRl = (l==0)?HR0:HR1;
    for (int s=0;s<20;s++){
      GemmP q{}; q.A=HRl; q.amode=4;
      q.B = sWhh + (size_t)l*2*256*256; q.bmode=1; q.ldb=256;
      q.C = HRl; q.epi=2;
      q.M=256; q.N=256; q.K=(s==0)?0:256;
      q.s=s; q.Tn=20; q.Hd=256;
      q.XP=XPH; q.bih=sbih + (size_t)l*2*256; q.bhh=sbhh + (size_t)l*2*256;
      launch_sm(q, 2);
    }
  }

  // object bidir RNN (hidden 512/dir)
  if (Ntot > 0) {
    for (int l=0;l<2;l++){
      GemmP p{}; p.A = (l==0)?ON:OR0; p.amode=0; p.lda=1024;
      p.B = aWih + (size_t)l*2*512*1024; p.bmode=1; p.ldb=1024;
      p.C = XPO; p.cmode=0; p.ldc=1024; p.M=Ntot*20; p.N=1024; p.K=1024;
      launch_big(p);
      float* ORl = (l==0)?OR0:OR1;
      for (int s=0;s<20;s++){
        GemmP q{}; q.A=ORl; q.amode=4;
        q.B = aWhh + (size_t)l*2*512*512; q.bmode=1; q.ldb=512;
        q.C = ORl; q.epi=2;
        q.M=Ntot; q.N=512; q.K=(s==0)?0:512;
        q.s=s; q.Tn=20; q.Hd=512;
        q.XP=XPO; q.bih=abih + (size_t)l*2*512; q.bhh=abhh + (size_t)l*2*512;
        launch_big(q, 2);
      }
    }
  }

  // heads
  { GemmP p{}; p.A=HR1; p.amode=0; p.lda=512; p.B=chW1; p.bmode=1; p.ldb=512;
    p.C=A1H; p.cmode=0; p.ldc=512; p.M=5120; p.N=512; p.K=512;
    p.epi=1; p.bias1=chb1; launch_big(p); }
  head_k<<<256,256>>>(A1H, chW2, chb2, out, 10);

  if (Ntot > 0) {
    GemmP p{}; p.A=OR1; p.amode=0; p.lda=1024; p.B=coW1; p.bmode=1; p.ldb=1024;
    p.C=A1O; p.cmode=0; p.ldc=512; p.M=Ntot*20; p.N=512; p.K=1024;
    p.epi=1; p.bias1=cob1; launch_big(p);
    head_k<<<Ntot,256>>>(A1O, coW2, cob2, out + 2560, 12);
  }
}

// round 3
// speedup vs baseline: 1.0733x; 1.0733x over previous
#include <cuda_runtime.h>
#include <math.h>

// B=256 T=20 NOBJ=5 D=2048 P=1000 IN=2018 H=512

// ------------------------- device scratch -------------------------
__device__ float g_MH [2048*512];
__device__ float g_MO [2048*512];
__device__ float g_CHv[512];
__device__ float g_COv[512];
__device__ float g_Y  [30720*512];
__device__ float g_G1 [30720*512];
__device__ float g_Z  [30720*512];
__device__ float g_SG [30720*512];
__device__ float g_HN [5120*512];
__device__ float g_ON [25600*1024];
__device__ float g_XPH[5120*512];
__device__ float g_HR0[5120*512];
__device__ float g_HR1[5120*512];
__device__ float g_XPO[25600*1024];
__device__ float g_OR0[25600*1024];
__device__ float g_OR1[25600*1024];
__device__ float g_A1H[5120*512];
__device__ float g_A1O[25600*512];
__device__ int   g_off[257];

// ---------------------------------------------------------------------------
// TF32 tensor-core GEMM (mma.sync m16n8k8), fp32 accumulate.
//  amode: 0 A[m*lda+k], 1 human-RF, 2 obj-RF, 3 A[k*lda+m], 4 RNN hprev
//  bmode: 0 B[k*ldb+n], 1 B[n*ldb+k]   (amode==4: Bp += d*Hd*Hd)
//  cmode: 0 crow=m, 1 crow=m*6, 2 obj row map
//  epi:   0 none, 1 bias+relu, 2 rnn step tanh(acc+XP+bih+bhh)
// ---------------------------------------------------------------------------
struct GemmP {
  const float* A; const float* B; float* C;
  int M, N, K;
  int amode, lda, bmode, ldb, cmode, ldc;
  int epi; const float* bias1;
  int s, Tn, Hd;
  const float* XP; const float* bih; const float* bhh;
};

__device__ __forceinline__ float to_tf32(float x){
  float r; asm("cvt.rna.tf32.f32 %0, %1;" : "=f"(r) : "f"(x)); return r;
}

__device__ __forceinline__ void mma8(float (&c)[4], const float (&a)[4], const float (&b)[2]){
  asm volatile(
    "mma.sync.aligned.m16n8k8.row.col.f32.tf32.tf32.f32 "
    "{%0,%1,%2,%3}, {%4,%5,%6,%7}, {%8,%9}, {%0,%1,%2,%3};\n"
    : "+f"(c[0]), "+f"(c[1]), "+f"(c[2]), "+f"(c[3])
    : "r"(__float_as_uint(a[0])), "r"(__float_as_uint(a[1])),
      "r"(__float_as_uint(a[2])), "r"(__float_as_uint(a[3])),
      "r"(__float_as_uint(b[0])), "r"(__float_as_uint(b[1])));
}

// BM=128, BN=64, BK=16; 256 threads = 8 warps in 4(m) x 2(n); warp tile 32x32.
__global__ __launch_bounds__(256) void mmagemm_k(GemmP p)
{
  const int BM=128, BN=64, BK=16;
  const int d = blockIdx.z;
  int t = 0, tprev = 0;
  if (p.amode == 4) { t = d ? (p.Tn - 1 - p.s) : p.s; tprev = d ? (t + 1) : (t - 1); }
  const int m0 = blockIdx.y * BM;
  const int n0 = blockIdx.x * BN;

  __shared__ float As[BK][BM+4];
  __shared__ float Bs[BK][BN+4];

  const int tid  = threadIdx.x;
  const int wid  = tid >> 5, lane = tid & 31;
  const int wm   = (wid & 3) * 32;     // warp m-offset within block
  const int wn   = (wid >> 2) * 32;    // warp n-offset within block
  const int gr   = lane >> 2;          // group row 0..7
  const int tg   = lane & 3;           // thread-in-group 0..3

  float acc[2][4][4];
#pragma unroll
  for (int i=0;i<2;i++)
#pragma unroll
    for (int j=0;j<4;j++)
#pragma unroll
      for (int r=0;r<4;r++) acc[i][j][r]=0.f;

  const float* Bp = p.B + ((p.amode==4) ? (size_t)d * p.Hd * p.Hd : (size_t)0);

  for (int k0 = 0; k0 < p.K; k0 += BK) {
    // ---- load A tile -> As[k][m] (tf32-rounded)
    for (int idx = tid; idx < BM*BK; idx += 256) {
      int kl, ml;
      if (p.amode == 3) { kl = idx / BM; ml = idx - kl*BM; }
      else              { ml = idx / BK; kl = idx - ml*BK; }
      int m = m0 + ml, k = k0 + kl;
      float v = 0.f;
      if (m < p.M && k < p.K) {
        if (p.amode == 0)      v = p.A[(size_t)m * p.lda + k];
        else if (p.amode == 1) { int b = m/20, tt = m - b*20;
                                 v = p.A[((size_t)(b*120 + tt))*2048 + k]; }
        else if (p.amode == 2) { int b = m/100, rm = m - b*100;
                                 int u = 1 + rm/20, tt = rm - (u-1)*20;
                                 v = p.A[((size_t)(b*120 + u*20 + tt))*2048 + k]; }
        else if (p.amode == 3) v = p.A[(size_t)k * p.lda + m];
        else                   v = p.A[((size_t)m * p.Tn + tprev)*(size_t)(2*p.Hd)
                                       + (size_t)d*p.Hd + k];
      }
      As[kl][ml] = to_tf32(v);
    }
    // ---- load B tile -> Bs[k][n] (tf32-rounded)
    for (int idx = tid; idx < BK*BN; idx += 256) {
      int kl, nl;
      if (p.bmode == 1) { nl = idx / BK; kl = idx - nl*BK; }
      else              { kl = idx / BN; nl = idx - kl*BN; }
      int k = k0 + kl, n = n0 + nl;
      float v = 0.f;
      if (k < p.K && n < p.N)
        v = (p.bmode==1) ? Bp[(size_t)n * p.ldb + k] : Bp[(size_t)k * p.ldb + n];
      Bs[kl][nl] = to_tf32(v);
    }
    __syncthreads();

#pragma unroll
    for (int kk = 0; kk < BK; kk += 8) {
      float a[2][4];
#pragma unroll
      for (int i=0;i<2;i++){
        int mrow = wm + i*16 + gr;
        a[i][0] = As[kk+tg  ][mrow];
        a[i][1] = As[kk+tg  ][mrow+8];
        a[i][2] = As[kk+tg+4][mrow];
        a[i][3] = As[kk+tg+4][mrow+8];
      }
      float b[4][2];
#pragma unroll
      for (int j=0;j<4;j++){
        int ncol = wn + j*8 + gr;
        b[j][0] = Bs[kk+tg  ][ncol];
        b[j][1] = Bs[kk+tg+4][ncol];
      }
#pragma unroll
      for (int i=0;i<2;i++)
#pragma unroll
        for (int j=0;j<4;j++) mma8(acc[i][j], a[i], b[j]);
    }
    __syncthreads();
  }

  // ---- epilogue
#pragma unroll
  for (int i=0;i<2;i++){
#pragma unroll
    for (int r=0;r<4;r++){
      int m = m0 + wm + i*16 + gr + ((r>=2)?8:0);
      if (m >= p.M) continue;
      size_t crow = 0;
      if (p.cmode == 0) crow = (size_t)m;
      else if (p.cmode == 1) crow = (size_t)m * 6;
      else if (p.cmode == 2) { int b = m/100, rm = m - b*100;
                               int u = 1 + rm/20, tt = rm - (u-1)*20;
                               crow = ((size_t)(b*20+tt))*6 + u; }
#pragma unroll
      for (int j=0;j<4;j++){
        int n = n0 + wn + j*8 + tg*2 + (r&1);
        if (n >= p.N) continue;
        float v = acc[i][j][r];
        if (p.epi == 2) {
          size_t o = ((size_t)m * p.Tn + t)*(size_t)(2*p.Hd) + (size_t)d*p.Hd + n;
          v += p.XP[o] + p.bih[d*p.Hd + n] + p.bhh[d*p.Hd + n];
          p.C[o] = tanhf(v);
        } else {
          if (p.epi == 1) { v += p.bias1[n]; v = fmaxf(v, 0.f); }
          p.C[crow * (size_t)p.ldc + n] = v;
        }
      }
    }
  }
}

// CH[h] = sum_p bph[p]*Wg1[4+p][h]; CO with bpo/Wg1[1004:2004]
__global__ void chco_k(const float* bph, const float* bpo, const float* Wg1,
                       float* CHv, float* COv)
{
  __shared__ float sa[256], sc[256];
  int hl = threadIdx.x & 31, sl = threadIdx.x >> 5;
  int h = blockIdx.x*32 + hl;
  float a=0.f, c=0.f;
  for (int q=0; q<125; q++){
    int pp = sl*125 + q;
    a += bph[pp]*Wg1[(size_t)(4+pp)*512 + h];
    c += bpo[pp]*Wg1[(size_t)(1004+pp)*512 + h];
  }
  sa[threadIdx.x]=a; sc[threadIdx.x]=c;
  __syncthreads();
  if (sl==0){
    for (int s2=1;s2<8;s2++){ a+=sa[s2*32+hl]; c+=sc[s2*32+hl]; }
    CHv[h]=a; COv[h]=c;
  }
}

// mix1: slivers + A_HAT mix + bg1 + relu
__global__ void mix1_k(const float* __restrict__ Y, const float* __restrict__ Wg1,
                       const float* __restrict__ bg1, const float* __restrict__ bbox,
                       const float* __restrict__ oh, const float* __restrict__ CHv,
                       const float* __restrict__ COv, float* __restrict__ G1)
{
  int bt = blockIdx.x; int b = bt/20, t = bt - b*20;
  __shared__ float sb[24], so[50];
  int tid = threadIdx.x;
  if (tid < 24) sb[tid] = bbox[((size_t)(b*6 + (tid>>2))*20 + t)*4 + (tid&3)];
  if (tid >= 32 && tid < 82) {
    int q = tid-32;
    so[q] = oh[((size_t)(b*5 + q/10)*20 + t)*10 + (q - (q/10)*10)];
  }
  __syncthreads();
  int h = tid;
  size_t base = (size_t)bt * 6 * 512;
  float y0 = Y[base + h] + CHv[h];
#pragma unroll
  for (int i=0;i<4;i++) y0 += sb[i]*Wg1[(size_t)i*512 + h];
  float ys = 0.f, yu[5];
#pragma unroll
  for (int u=1; u<=5; u++){
    float v = Y[base + (size_t)u*512 + h] + COv[h];
#pragma unroll
    for (int i=0;i<4;i++) v += sb[u*4+i]*Wg1[(size_t)(2004+i)*512 + h];
#pragma unroll
    for (int j=0;j<10;j++) v += so[(u-1)*10+j]*Wg1[(size_t)(2008+j)*512 + h];
    yu[u-1]=v; ys += v;
  }
  const float R6 = 1.f/6.f, R12 = 0.28867513459481287f;
  float bg = bg1[h];
  G1[base + h] = fmaxf(R6*y0 + R12*ys + bg, 0.f);
#pragma unroll
  for (int u=1;u<=5;u++)
    G1[base + (size_t)u*512 + h] = fmaxf(R12*y0 + 0.5f*yu[u-1] + bg, 0.f);
}

// mix2: A_HAT mix + bg2 + relu -> SG; extract human node -> HN
__global__ void mix2_k(const float* __restrict__ Z, const float* __restrict__ bg2,
                       float* __restrict__ SG, float* __restrict__ HN)
{
  int bt = blockIdx.x;
  int h = threadIdx.x;
  size_t base = (size_t)bt*6*512;
  float z0 = Z[base+h];
  float zs=0.f, zu[5];
#pragma unroll
  for (int u=1;u<=5;u++){ float v = Z[base+(size_t)u*512+h]; zu[u-1]=v; zs+=v; }
  const float R6 = 1.f/6.f, R12 = 0.28867513459481287f;
  float bg = bg2[h];
  float g0 = fmaxf(R6*z0 + R12*zs + bg, 0.f);
  SG[base+h]=g0;
  HN[(size_t)bt*512+h]=g0;
#pragma unroll
  for (int u=1;u<=5;u++)
    SG[base+(size_t)u*512+h] = fmaxf(R12*z0 + 0.5f*zu[u-1] + bg, 0.f);
}

__global__ void prefix_k(const int* num, int* off){
  if (threadIdx.x==0){
    int a=0;
    for (int b=0;b<256;b++){ off[b]=a; a+=num[b]; }
    off[256]=a;
  }
}

__global__ void gather_k(const float* __restrict__ SG, const int* __restrict__ num,
                         const int* __restrict__ off, float* __restrict__ ON)
{
  int bk = blockIdx.x; int b = bk/5, k = bk - b*5;
  if (k >= num[b]) return;
  int t = blockIdx.y;
  int r = off[b] + k;
  size_t ob  = ((size_t)r*20 + t)*1024;
  size_t sgb = ((size_t)(b*20+t))*6*512;
  int h = threadIdx.x;
  ON[ob + h]       = SG[sgb + h];
  ON[ob + 512 + h] = SG[sgb + (size_t)(k+1)*512 + h];
}

// out[r,i] = (sum_t A1[r,t,:]) . W2[i,:] + 20*b2[i]
__global__ void head_k(const float* __restrict__ A1, const float* __restrict__ W2,
                       const float* __restrict__ b2, float* __restrict__ out, int nout)
{
  int r = blockIdx.x;
  __shared__ float cs[512];
  __shared__ float red[256];
  int tid = threadIdx.x;
  for (int j = tid; j < 512; j += 256){
    float s = 0.f;
    for (int t=0;t<20;t++) s += A1[((size_t)r*20 + t)*512 + j];
    cs[j] = s;
  }
  __syncthreads();
  for (int i=0;i<nout;i++){
    float v = cs[tid]*W2[(size_t)i*512+tid] + cs[tid+256]*W2[(size_t)i*512+tid+256];
    red[tid]=v; __syncthreads();
    for (int st=128; st>0; st>>=1){ if (tid<st) red[tid]+=red[tid+st]; __syncthreads(); }
    if (tid==0) out[(size_t)r*nout + i] = red[0] + 20.f*b2[i];
    __syncthreads();
  }
}

// ------------------------------- host side ---------------------------------
static inline void launch_mma(const GemmP& p, int z = 1){
  dim3 g((unsigned)((p.N+63)/64), (unsigned)((p.M+127)/128), (unsigned)z);
  mmagemm_k<<<g,256>>>(p);
}

extern "C" void kernel_launch(void* const* d_in, const int* in_sizes, int n_in,
                              void* d_out, int out_size)
{
  const float* one_hot = (const float*)d_in[0];
  const float* bbox    = (const float*)d_in[1];
  const int*   numobj  = (const int*)  d_in[2];
  const float* rf      = (const float*)d_in[3];
  const float* Wph  = (const float*)d_in[4];
  const float* bph  = (const float*)d_in[5];
  const float* Wpo  = (const float*)d_in[6];
  const float* bpo  = (const float*)d_in[7];
  const float* Wg1  = (const float*)d_in[8];
  const float* bg1  = (const float*)d_in[9];
  const float* Wg2  = (const float*)d_in[10];
  const float* bg2  = (const float*)d_in[11];
  const float* sWih = (const float*)d_in[12];
  const float* sWhh = (const float*)d_in[13];
  const float* sbih = (const float*)d_in[14];
  const float* sbhh = (const float*)d_in[15];
  const float* aWih = (const float*)d_in[16];
  const float* aWhh = (const float*)d_in[17];
  const float* abih = (const float*)d_in[18];
  const float* abhh = (const float*)d_in[19];
  const float* chW1 = (const float*)d_in[20];
  const float* chb1 = (const float*)d_in[21];
  const float* chW2 = (const float*)d_in[22];
  const float* chb2 = (const float*)d_in[23];
  const float* coW1 = (const float*)d_in[24];
  const float* cob1 = (const float*)d_in[25];
  const float* coW2 = (const float*)d_in[26];
  const float* cob2 = (const float*)d_in[27];
  float* out = (float*)d_out;

  int Ntot = (out_size - 2560) / 12;
  if (Ntot < 0) Ntot = 0; if (Ntot > 1280) Ntot = 1280;

  float *MH,*MO,*CHv,*COv,*Y,*G1,*Z,*SG,*HN,*ON,*XPH,*HR0,*HR1,*XPO,*OR0,*OR1,*A1H,*A1O;
  int *off;
  cudaGetSymbolAddress((void**)&MH,  g_MH);
  cudaGetSymbolAddress((void**)&MO,  g_MO);
  cudaGetSymbolAddress((void**)&CHv, g_CHv);
  cudaGetSymbolAddress((void**)&COv, g_COv);
  cudaGetSymbolAddress((void**)&Y,   g_Y);
  cudaGetSymbolAddress((void**)&G1,  g_G1);
  cudaGetSymbolAddress((void**)&Z,   g_Z);
  cudaGetSymbolAddress((void**)&SG,  g_SG);
  cudaGetSymbolAddress((void**)&HN,  g_HN);
  cudaGetSymbolAddress((void**)&ON,  g_ON);
  cudaGetSymbolAddress((void**)&XPH, g_XPH);
  cudaGetSymbolAddress((void**)&HR0, g_HR0);
  cudaGetSymbolAddress((void**)&HR1, g_HR1);
  cudaGetSymbolAddress((void**)&XPO, g_XPO);
  cudaGetSymbolAddress((void**)&OR0, g_OR0);
  cudaGetSymbolAddress((void**)&OR1, g_OR1);
  cudaGetSymbolAddress((void**)&A1H, g_A1H);
  cudaGetSymbolAddress((void**)&A1O, g_A1O);
  cudaGetSymbolAddress((void**)&off, g_off);

  // MH = Wph^T @ Wg1[4:1004] ; MO = Wpo^T @ Wg1[1004:2004]
  { GemmP p{}; p.A=Wph; p.amode=3; p.lda=2048; p.B=Wg1+4*512; p.bmode=0; p.ldb=512;
    p.C=MH; p.cmode=0; p.ldc=512; p.M=2048; p.N=512; p.K=1000; launch_mma(p); }
  { GemmP p{}; p.A=Wpo; p.amode=3; p.lda=2048; p.B=Wg1+1004*512; p.bmode=0; p.ldb=512;
    p.C=MO; p.cmode=0; p.ldc=512; p.M=2048; p.N=512; p.K=1000; launch_mma(p); }
  chco_k<<<16,256>>>(bph, bpo, Wg1, CHv, COv);

  // Y = rf @ M  (written [b,t,u,512])
  { GemmP p{}; p.A=rf; p.amode=1; p.B=MH; p.bmode=0; p.ldb=512;
    p.C=Y; p.cmode=1; p.ldc=512; p.M=5120; p.N=512; p.K=2048; launch_mma(p); }
  { GemmP p{}; p.A=rf; p.amode=2; p.B=MO; p.bmode=0; p.ldb=512;
    p.C=Y; p.cmode=2; p.ldc=512; p.M=25600; p.N=512; p.K=2048; launch_mma(p); }
  mix1_k<<<5120,512>>>(Y, Wg1, bg1, bbox, one_hot, CHv, COv, G1);

  // Z = G1 @ Wg2 -> mix2 -> SG, HN
  { GemmP p{}; p.A=G1; p.amode=0; p.lda=512; p.B=Wg2; p.bmode=0; p.ldb=512;
    p.C=Z; p.cmode=0; p.ldc=512; p.M=30720; p.N=512; p.K=512; launch_mma(p); }
  mix2_k<<<5120,512>>>(Z, bg2, SG, HN);

  prefix_k<<<1,32>>>(numobj, off);
  gather_k<<<dim3(1280,20),512>>>(SG, numobj, off, ON);

  // human bidir RNN (hidden 256/dir)
  for (int l=0;l<2;l++){
    GemmP p{}; p.A = (l==0)?HN:HR0; p.amode=0; p.lda=512;
    p.B = sWih + (size_t)l*2*256*512; p.bmode=1; p.ldb=512;
    p.C = XPH; p.cmode=0; p.ldc=512; p.M=5120; p.N=512; p.K=512;
    launch_mma(p);
    float* HRl = (l==0)?HR0:HR1;
    for (int s=0;s<20;s++){
      GemmP q{}; q.A=HRl; q.amode=4;
      q.B = sWhh + (size_t)l*2*256*256; q.bmode=1; q.ldb=256;
      q.C = HRl; q.epi=2;
      q.M=256; q.N=256; q.K=(s==0)?0:256;
      q.s=s; q.Tn=20; q.Hd=256;
      q.XP=XPH; q.bih=sbih + (size_t)l*2*256; q.bhh=sbhh + (size_t)l*2*256;
      launch_mma(q, 2);
    }
  }

  // object bidir RNN (hidden 512/dir)
  if (Ntot > 0) {
    for (int l=0;l<2;l++){
      GemmP p{}; p.A = (l==0)?ON:OR0; p.amode=0; p.lda=1024;
      p.B = aWih + (size_t)l*2*512*1024; p.bmode=1; p.ldb=1024;
      p.C = XPO; p.cmode=0; p.ldc=1024; p.M=Ntot*20; p.N=1024; p.K=1024;
      launch_mma(p);
      float* ORl = (l==0)?OR0:OR1;
      for (int s=0;s<20;s++){
        GemmP q{}; q.A=ORl; q.amode=4;
        q.B = aWhh + (size_t)l*2*512*512; q.bmode=1; q.ldb=512;
        q.C = ORl; q.epi=2;
        q.M=Ntot; q.N=512; q.K=(s==0)?0:512;
        q.s=s; q.Tn=20; q.Hd=512;
        q.XP=XPO; q.bih=abih + (size_t)l*2*512; q.bhh=abhh + (size_t)l*2*512;
        launch_mma(q, 2);
      }
    }
  }

  // heads
  { GemmP p{}; p.A=HR1; p.amode=0; p.lda=512; p.B=chW1; p.bmode=1; p.ldb=512;
    p.C=A1H; p.cmode=0; p.ldc=512; p.M=5120; p.N=512; p.K=512;
    p.epi=1; p.bias1=chb1; launch_mma(p); }
  head_k<<<256,256>>>(A1H, chW2, chb2, out, 10);

  if (Ntot > 0) {
    GemmP p{}; p.A=OR1; p.amode=0; p.lda=1024; p.B=coW1; p.bmode=1; p.ldb=1024;
    p.C=A1O; p.cmode=0; p.ldc=512; p.M=Ntot*20; p.N=512; p.K=1024;
    p.epi=1; p.bias1=cob1; launch_mma(p);
    head_k<<<Ntot,256>>>(A1O, coW2, cob2, out + 2560, 12);
  }
}

// round 4
// speedup vs baseline: 2.4330x; 2.2668x over previous
#include <cuda_runtime.h>
#include <math.h>

// B=256 T=20 NOBJ=5 D=2048 P=1000 IN=2018 H=512

// ------------------------- device scratch -------------------------
__device__ float g_MH [2048*512];
__device__ float g_MO [2048*512];
__device__ float g_CHv[512];
__device__ float g_COv[512];
__device__ float g_Y  [30720*512];
__device__ float g_G1 [30720*512];
__device__ float g_Z  [30720*512];
__device__ float g_SG [30720*512];
__device__ float g_HN [5120*512];
__device__ float g_ON [25600*1024];
__device__ float g_XPH[5120*512];
__device__ float g_HR0[5120*512];
__device__ float g_HR1[5120*512];
__device__ float g_XPO[25600*1024];
__device__ float g_OR0[25600*1024];
__device__ float g_OR1[25600*1024];
__device__ float g_A1H[5120*512];
__device__ float g_A1O[25600*512];
__device__ int   g_off[257];

struct GemmP {
  const float* A; const float* B; float* C;
  int M, N, K;
  int lda, ldb, ldc;
  const float* bias1;
};

__device__ __forceinline__ float to_tf32(float x){
  float r; asm("cvt.rna.tf32.f32 %0, %1;" : "=f"(r) : "f"(x)); return r;
}

__device__ __forceinline__ void mma8(float (&c)[4], const float (&a)[4], const float (&b)[2]){
  asm volatile(
    "mma.sync.aligned.m16n8k8.row.col.f32.tf32.tf32.f32 "
    "{%0,%1,%2,%3}, {%4,%5,%6,%7}, {%8,%9}, {%0,%1,%2,%3};\n"
    : "+f"(c[0]), "+f"(c[1]), "+f"(c[2]), "+f"(c[3])
    : "r"(__float_as_uint(a[0])), "r"(__float_as_uint(a[1])),
      "r"(__float_as_uint(a[2])), "r"(__float_as_uint(a[3])),
      "r"(__float_as_uint(b[0])), "r"(__float_as_uint(b[1])));
}

// ---------------------------------------------------------------------------
// Fast tf32 GEMM: BM=128, BN=128, BK=16; 8 warps (2m x 4n), warp tile 64x32.
//  AMODE: 0 A[m*lda+k], 1 human-RF rows, 2 obj-RF rows, 3 A[k*lda+m]
//  BMODE: 0 B[k*ldb+n], 1 B[n*ldb+k]
//  CMODE: 0 crow=m, 1 crow=m*6, 2 obj row map
//  EPI:   0 none, 1 bias+relu
// ---------------------------------------------------------------------------
template<int AMODE,int BMODE,int CMODE,int EPI>
__global__ __launch_bounds__(256) void fgemm_k(GemmP p)
{
  __shared__ float As[16][136];
  __shared__ float Bs[16][136];
  const int m0 = blockIdx.y * 128;
  const int n0 = blockIdx.x * 128;
  const int tid = threadIdx.x, wid = tid>>5, lane = tid&31;
  const int gr = lane>>2, tg = lane&3;
  const int wm = (wid&1)*64, wn = (wid>>1)*32;

  float acc[4][4][4];
#pragma unroll
  for (int i=0;i<4;i++)
#pragma unroll
    for (int j=0;j<4;j++)
#pragma unroll
      for (int r=0;r<4;r++) acc[i][j][r]=0.f;

  for (int k0 = 0; k0 < p.K; k0 += 16) {
    // ---- A tile -> As[k][m]
    if (AMODE == 3) {
      for (int idx=tid; idx<512; idx+=256){
        int kl=idx>>5, mq=idx&31; int k=k0+kl, m=m0+mq*4;
        float4 v = make_float4(0.f,0.f,0.f,0.f);
        if (k < p.K && m+3 < p.M) v = *(const float4*)&p.A[(size_t)k*p.lda + m];
        float4 w; w.x=to_tf32(v.x); w.y=to_tf32(v.y); w.z=to_tf32(v.z); w.w=to_tf32(v.w);
        *(float4*)&As[kl][mq*4] = w;
      }
    } else {
      for (int idx=tid; idx<512; idx+=256){
        int row=idx>>2, kq=idx&3; int m=m0+row, k=k0+kq*4;
        float4 v = make_float4(0.f,0.f,0.f,0.f);
        if (m < p.M && k < p.K) {
          size_t base;
          if (AMODE==0) base = (size_t)m * p.lda;
          else if (AMODE==1){ int b=m/20, tt=m-b*20; base=((size_t)(b*120+tt))*2048; }
          else { int b=m/100, rm=m-b*100; int u=1+rm/20, tt=rm-(u-1)*20;
                 base=((size_t)(b*120+u*20+tt))*2048; }
          v = *(const float4*)&p.A[base + k];
        }
        As[kq*4+0][row]=to_tf32(v.x);
        As[kq*4+1][row]=to_tf32(v.y);
        As[kq*4+2][row]=to_tf32(v.z);
        As[kq*4+3][row]=to_tf32(v.w);
      }
    }
    // ---- B tile -> Bs[k][n]
    if (BMODE == 0) {
      for (int idx=tid; idx<512; idx+=256){
        int kl=idx>>5, nq=idx&31; int k=k0+kl, n=n0+nq*4;
        float4 v = make_float4(0.f,0.f,0.f,0.f);
        if (k < p.K && n < p.N) v = *(const float4*)&p.B[(size_t)k*p.ldb + n];
        float4 w; w.x=to_tf32(v.x); w.y=to_tf32(v.y); w.z=to_tf32(v.z); w.w=to_tf32(v.w);
        *(float4*)&Bs[kl][nq*4] = w;
      }
    } else {
      for (int idx=tid; idx<512; idx+=256){
        int nl=idx>>2, kq=idx&3; int n=n0+nl, k=k0+kq*4;
        float4 v = make_float4(0.f,0.f,0.f,0.f);
        if (n < p.N && k < p.K) v = *(const float4*)&p.B[(size_t)n*p.ldb + k];
        Bs[kq*4+0][nl]=to_tf32(v.x);
        Bs[kq*4+1][nl]=to_tf32(v.y);
        Bs[kq*4+2][nl]=to_tf32(v.z);
        Bs[kq*4+3][nl]=to_tf32(v.w);
      }
    }
    __syncthreads();

#pragma unroll
    for (int kk=0; kk<16; kk+=8){
      float a[4][4];
#pragma unroll
      for (int i=0;i<4;i++){
        int mr = wm + i*16 + gr;
        a[i][0]=As[kk+tg  ][mr];   a[i][1]=As[kk+tg  ][mr+8];
        a[i][2]=As[kk+tg+4][mr];   a[i][3]=As[kk+tg+4][mr+8];
      }
      float b[4][2];
#pragma unroll
      for (int j=0;j<4;j++){
        int nc = wn + j*8 + gr;
        b[j][0]=Bs[kk+tg][nc];  b[j][1]=Bs[kk+tg+4][nc];
      }
#pragma unroll
      for (int i=0;i<4;i++)
#pragma unroll
        for (int j=0;j<4;j++) mma8(acc[i][j], a[i], b[j]);
    }
    __syncthreads();
  }

  // ---- epilogue
#pragma unroll
  for (int i=0;i<4;i++){
#pragma unroll
    for (int r=0;r<4;r++){
      int m = m0 + wm + i*16 + gr + ((r>=2)?8:0);
      if (m >= p.M) continue;
      size_t crow;
      if (CMODE==0) crow = (size_t)m;
      else if (CMODE==1) crow = (size_t)m * 6;
      else { int b=m/100, rm=m-b*100; int u=1+rm/20, tt=rm-(u-1)*20;
             crow = ((size_t)(b*20+tt))*6 + u; }
#pragma unroll
      for (int j=0;j<4;j++){
        int n = n0 + wn + j*8 + tg*2 + (r&1);
        if (n >= p.N) continue;
        float v = acc[i][j][r];
        if (EPI==1){ v += p.bias1[n]; v = fmaxf(v, 0.f); }
        p.C[crow*(size_t)p.ldc + n] = v;
      }
    }
  }
}

// ---------------------------------------------------------------------------
// Persistent fused bidir RNN layer: block owns 32 rows, loops 20 steps.
//  XP/OUT layout: [m][t][2*HD], dir slice d*HD.  Whh: [2][HD][HD] (n-major).
// ---------------------------------------------------------------------------
template<int HD>
__global__ __launch_bounds__(256) void rnnfuse_k(const float* __restrict__ XP,
    const float* __restrict__ Whh, const float* __restrict__ bih,
    const float* __restrict__ bhh, float* __restrict__ OUT, int M)
{
  constexpr int HP = HD+4;   // hs stride (stride%32==4 -> conflict-free a-frags)
  constexpr int BP = HD+8;   // Bs stride (stride%32==8 -> conflict-free b-frags)
  constexpr int NJ = HD/64;  // n8-tiles per warp
  extern __shared__ float sm[];
  float* hs  = sm;             // [32][HP]
  float* Bsm = sm + 32*HP;     // [16][BP]

  const int d  = blockIdx.z;
  const int r0 = blockIdx.x*32;
  const int tid = threadIdx.x, wid = tid>>5, lane = tid&31;
  const int gr = lane>>2, tg = lane&3;
  const int wn = wid*(HD/8);
  const float* Bp = Whh + (size_t)d*HD*HD;

  float bb[NJ][2];
#pragma unroll
  for (int j=0;j<NJ;j++){
    int n = wn + j*8 + tg*2;
    bb[j][0] = bih[d*HD+n]   + bhh[d*HD+n];
    bb[j][1] = bih[d*HD+n+1] + bhh[d*HD+n+1];
  }

  for (int s=0; s<20; s++){
    int t = d ? (19 - s) : s;
    float acc[2][NJ][4];
#pragma unroll
    for (int i=0;i<2;i++)
#pragma unroll
      for (int j=0;j<NJ;j++)
#pragma unroll
        for (int r=0;r<4;r++) acc[i][j][r]=0.f;

    if (s > 0){
      for (int k0=0; k0<HD; k0+=16){
        __syncthreads();
        for (int idx=tid; idx<HD*4; idx+=256){
          int nl=idx>>2, kq=idx&3;
          float4 v = *(const float4*)&Bp[(size_t)nl*HD + k0 + kq*4];
          Bsm[(kq*4+0)*BP + nl]=to_tf32(v.x);
          Bsm[(kq*4+1)*BP + nl]=to_tf32(v.y);
          Bsm[(kq*4+2)*BP + nl]=to_tf32(v.z);
          Bsm[(kq*4+3)*BP + nl]=to_tf32(v.w);
        }
        __syncthreads();
#pragma unroll
        for (int kk=0; kk<16; kk+=8){
          float a[2][4];
#pragma unroll
          for (int i=0;i<2;i++){
            int lr = i*16 + gr;
            a[i][0]=hs[ lr   *HP + k0+kk+tg  ];
            a[i][1]=hs[(lr+8)*HP + k0+kk+tg  ];
            a[i][2]=hs[ lr   *HP + k0+kk+tg+4];
            a[i][3]=hs[(lr+8)*HP + k0+kk+tg+4];
          }
          float b[NJ][2];
#pragma unroll
          for (int j=0;j<NJ;j++){
            int nc = wn + j*8 + gr;
            b[j][0]=Bsm[(kk+tg  )*BP + nc];
            b[j][1]=Bsm[(kk+tg+4)*BP + nc];
          }
#pragma unroll
          for (int i=0;i<2;i++)
#pragma unroll
            for (int j=0;j<NJ;j++) mma8(acc[i][j], a[i], b[j]);
        }
      }
    }
    __syncthreads();   // all frag reads done before hs is overwritten
#pragma unroll
    for (int i=0;i<2;i++)
#pragma unroll
      for (int r=0;r<4;r++){
        int lm = i*16 + gr + ((r>=2)?8:0);
        int m  = r0 + lm;
#pragma unroll
        for (int j=0;j<NJ;j++){
          int n = wn + j*8 + tg*2 + (r&1);
          if (m < M){
            size_t o = ((size_t)m*20 + t)*(size_t)(2*HD) + (size_t)d*HD + n;
            float v = tanhf(acc[i][j][r] + XP[o] + bb[j][r&1]);
            OUT[o] = v;
            hs[lm*HP + n] = to_tf32(v);
          } else {
            hs[lm*HP + n] = 0.f;
          }
        }
      }
  }
}

// CH[h] = sum_p bph[p]*Wg1[4+p][h]; CO with bpo/Wg1[1004:2004]
__global__ void chco_k(const float* bph, const float* bpo, const float* Wg1,
                       float* CHv, float* COv)
{
  __shared__ float sa[256], sc[256];
  int hl = threadIdx.x & 31, sl = threadIdx.x >> 5;
  int h = blockIdx.x*32 + hl;
  float a=0.f, c=0.f;
  for (int q=0; q<125; q++){
    int pp = sl*125 + q;
    a += bph[pp]*Wg1[(size_t)(4+pp)*512 + h];
    c += bpo[pp]*Wg1[(size_t)(1004+pp)*512 + h];
  }
  sa[threadIdx.x]=a; sc[threadIdx.x]=c;
  __syncthreads();
  if (sl==0){
    for (int s2=1;s2<8;s2++){ a+=sa[s2*32+hl]; c+=sc[s2*32+hl]; }
    CHv[h]=a; COv[h]=c;
  }
}

__global__ void mix1_k(const float* __restrict__ Y, const float* __restrict__ Wg1,
                       const float* __restrict__ bg1, const float* __restrict__ bbox,
                       const float* __restrict__ oh, const float* __restrict__ CHv,
                       const float* __restrict__ COv, float* __restrict__ G1)
{
  int bt = blockIdx.x; int b = bt/20, t = bt - b*20;
  __shared__ float sb[24], so[50];
  int tid = threadIdx.x;
  if (tid < 24) sb[tid] = bbox[((size_t)(b*6 + (tid>>2))*20 + t)*4 + (tid&3)];
  if (tid >= 32 && tid < 82) {
    int q = tid-32;
    so[q] = oh[((size_t)(b*5 + q/10)*20 + t)*10 + (q - (q/10)*10)];
  }
  __syncthreads();
  int h = tid;
  size_t base = (size_t)bt * 6 * 512;
  float y0 = Y[base + h] + CHv[h];
#pragma unroll
  for (int i=0;i<4;i++) y0 += sb[i]*Wg1[(size_t)i*512 + h];
  float ys = 0.f, yu[5];
#pragma unroll
  for (int u=1; u<=5; u++){
    float v = Y[base + (size_t)u*512 + h] + COv[h];
#pragma unroll
    for (int i=0;i<4;i++) v += sb[u*4+i]*Wg1[(size_t)(2004+i)*512 + h];
#pragma unroll
    for (int j=0;j<10;j++) v += so[(u-1)*10+j]*Wg1[(size_t)(2008+j)*512 + h];
    yu[u-1]=v; ys += v;
  }
  const float R6 = 1.f/6.f, R12 = 0.28867513459481287f;
  float bg = bg1[h];
  G1[base + h] = fmaxf(R6*y0 + R12*ys + bg, 0.f);
#pragma unroll
  for (int u=1;u<=5;u++)
    G1[base + (size_t)u*512 + h] = fmaxf(R12*y0 + 0.5f*yu[u-1] + bg, 0.f);
}

__global__ void mix2_k(const float* __restrict__ Z, const float* __restrict__ bg2,
                       float* __restrict__ SG, float* __restrict__ HN)
{
  int bt = blockIdx.x;
  int h = threadIdx.x;
  size_t base = (size_t)bt*6*512;
  float z0 = Z[base+h];
  float zs=0.f, zu[5];
#pragma unroll
  for (int u=1;u<=5;u++){ float v = Z[base+(size_t)u*512+h]; zu[u-1]=v; zs+=v; }
  const float R6 = 1.f/6.f, R12 = 0.28867513459481287f;
  float bg = bg2[h];
  float g0 = fmaxf(R6*z0 + R12*zs + bg, 0.f);
  SG[base+h]=g0;
  HN[(size_t)bt*512+h]=g0;
#pragma unroll
  for (int u=1;u<=5;u++)
    SG[base+(size_t)u*512+h] = fmaxf(R12*z0 + 0.5f*zu[u-1] + bg, 0.f);
}

__global__ void prefix_k(const int* num, int* off){
  if (threadIdx.x==0){
    int a=0;
    for (int b=0;b<256;b++){ off[b]=a; a+=num[b]; }
    off[256]=a;
  }
}

__global__ void gather_k(const float* __restrict__ SG, const int* __restrict__ num,
                         const int* __restrict__ off, float* __restrict__ ON)
{
  int bk = blockIdx.x; int b = bk/5, k = bk - b*5;
  if (k >= num[b]) return;
  int t = blockIdx.y;
  int r = off[b] + k;
  size_t ob  = ((size_t)r*20 + t)*1024;
  size_t sgb = ((size_t)(b*20+t))*6*512;
  int h = threadIdx.x;
  ON[ob + h]       = SG[sgb + h];
  ON[ob + 512 + h] = SG[sgb + (size_t)(k+1)*512 + h];
}

__global__ void head_k(const float* __restrict__ A1, const float* __restrict__ W2,
                       const float* __restrict__ b2, float* __restrict__ out, int nout)
{
  int r = blockIdx.x;
  __shared__ float cs[512];
  __shared__ float red[256];
  int tid = threadIdx.x;
  for (int j = tid; j < 512; j += 256){
    float s = 0.f;
    for (int t=0;t<20;t++) s += A1[((size_t)r*20 + t)*512 + j];
    cs[j] = s;
  }
  __syncthreads();
  for (int i=0;i<nout;i++){
    float v = cs[tid]*W2[(size_t)i*512+tid] + cs[tid+256]*W2[(size_t)i*512+tid+256];
    red[tid]=v; __syncthreads();
    for (int st=128; st>0; st>>=1){ if (tid<st) red[tid]+=red[tid+st]; __syncthreads(); }
    if (tid==0) out[(size_t)r*nout + i] = red[0] + 20.f*b2[i];
    __syncthreads();
  }
}

// ------------------------------- host side ---------------------------------
template<int AM,int BM2,int CM,int EP>
static inline void launch_f(const GemmP& p){
  dim3 g((unsigned)((p.N+127)/128), (unsigned)((p.M+127)/128), 1);
  fgemm_k<AM,BM2,CM,EP><<<g,256>>>(p);
}

extern "C" void kernel_launch(void* const* d_in, const int* in_sizes, int n_in,
                              void* d_out, int out_size)
{
  const float* one_hot = (const float*)d_in[0];
  const float* bbox    = (const float*)d_in[1];
  const int*   numobj  = (const int*)  d_in[2];
  const float* rf      = (const float*)d_in[3];
  const float* Wph  = (const float*)d_in[4];
  const float* bph  = (const float*)d_in[5];
  const float* Wpo  = (const float*)d_in[6];
  const float* bpo  = (const float*)d_in[7];
  const float* Wg1  = (const float*)d_in[8];
  const float* bg1  = (const float*)d_in[9];
  const float* Wg2  = (const float*)d_in[10];
  const float* bg2  = (const float*)d_in[11];
  const float* sWih = (const float*)d_in[12];
  const float* sWhh = (const float*)d_in[13];
  const float* sbih = (const float*)d_in[14];
  const float* sbhh = (const float*)d_in[15];
  const float* aWih = (const float*)d_in[16];
  const float* aWhh = (const float*)d_in[17];
  const float* abih = (const float*)d_in[18];
  const float* abhh = (const float*)d_in[19];
  const float* chW1 = (const float*)d_in[20];
  const float* chb1 = (const float*)d_in[21];
  const float* chW2 = (const float*)d_in[22];
  const float* chb2 = (const float*)d_in[23];
  const float* coW1 = (const float*)d_in[24];
  const float* cob1 = (const float*)d_in[25];
  const float* coW2 = (const float*)d_in[26];
  const float* cob2 = (const float*)d_in[27];
  float* out = (float*)d_out;

  int Ntot = (out_size - 2560) / 12;
  if (Ntot < 0) Ntot = 0; if (Ntot > 1280) Ntot = 1280;

  float *MH,*MO,*CHv,*COv,*Y,*G1,*Z,*SG,*HN,*ON,*XPH,*HR0,*HR1,*XPO,*OR0,*OR1,*A1H,*A1O;
  int *off;
  cudaGetSymbolAddress((void**)&MH,  g_MH);
  cudaGetSymbolAddress((void**)&MO,  g_MO);
  cudaGetSymbolAddress((void**)&CHv, g_CHv);
  cudaGetSymbolAddress((void**)&COv, g_COv);
  cudaGetSymbolAddress((void**)&Y,   g_Y);
  cudaGetSymbolAddress((void**)&G1,  g_G1);
  cudaGetSymbolAddress((void**)&Z,   g_Z);
  cudaGetSymbolAddress((void**)&SG,  g_SG);
  cudaGetSymbolAddress((void**)&HN,  g_HN);
  cudaGetSymbolAddress((void**)&ON,  g_ON);
  cudaGetSymbolAddress((void**)&XPH, g_XPH);
  cudaGetSymbolAddress((void**)&HR0, g_HR0);
  cudaGetSymbolAddress((void**)&HR1, g_HR1);
  cudaGetSymbolAddress((void**)&XPO, g_XPO);
  cudaGetSymbolAddress((void**)&OR0, g_OR0);
  cudaGetSymbolAddress((void**)&OR1, g_OR1);
  cudaGetSymbolAddress((void**)&A1H, g_A1H);
  cudaGetSymbolAddress((void**)&A1O, g_A1O);
  cudaGetSymbolAddress((void**)&off, g_off);

  // allow big dynamic smem for fused RNN kernels (idempotent host-side calls)
  const int SMEM512 = 32*(512+4)*4 + 16*(512+8)*4;  // 99,328 B
  const int SMEM256 = 32*(256+4)*4 + 16*(256+8)*4;  // 50,176 B
  cudaFuncSetAttribute(rnnfuse_k<512>, cudaFuncAttributeMaxDynamicSharedMemorySize, SMEM512);
  cudaFuncSetAttribute(rnnfuse_k<256>, cudaFuncAttributeMaxDynamicSharedMemorySize, SMEM256);

  // MH = Wph^T @ Wg1[4:1004] ; MO = Wpo^T @ Wg1[1004:2004]
  { GemmP p{}; p.A=Wph; p.lda=2048; p.B=Wg1+4*512; p.ldb=512;
    p.C=MH; p.ldc=512; p.M=2048; p.N=512; p.K=1000; launch_f<3,0,0,0>(p); }
  { GemmP p{}; p.A=Wpo; p.lda=2048; p.B=Wg1+1004*512; p.ldb=512;
    p.C=MO; p.ldc=512; p.M=2048; p.N=512; p.K=1000; launch_f<3,0,0,0>(p); }
  chco_k<<<16,256>>>(bph, bpo, Wg1, CHv, COv);

  // Y = rf @ M  (written [b,t,u,512])
  { GemmP p{}; p.A=rf; p.B=MH; p.ldb=512;
    p.C=Y; p.ldc=512; p.M=5120; p.N=512; p.K=2048; launch_f<1,0,1,0>(p); }
  { GemmP p{}; p.A=rf; p.B=MO; p.ldb=512;
    p.C=Y; p.ldc=512; p.M=25600; p.N=512; p.K=2048; launch_f<2,0,2,0>(p); }
  mix1_k<<<5120,512>>>(Y, Wg1, bg1, bbox, one_hot, CHv, COv, G1);

  // Z = G1 @ Wg2 -> mix2 -> SG, HN
  { GemmP p{}; p.A=G1; p.lda=512; p.B=Wg2; p.ldb=512;
    p.C=Z; p.ldc=512; p.M=30720; p.N=512; p.K=512; launch_f<0,0,0,0>(p); }
  mix2_k<<<5120,512>>>(Z, bg2, SG, HN);

  prefix_k<<<1,32>>>(numobj, off);
  gather_k<<<dim3(1280,20),512>>>(SG, numobj, off, ON);

  // human bidir RNN (hidden 256/dir): input GEMM + fused 20-step kernel
  for (int l=0;l<2;l++){
    GemmP p{}; p.A = (l==0)?HN:HR0; p.lda=512;
    p.B = sWih + (size_t)l*2*256*512; p.ldb=512;
    p.C = XPH; p.ldc=512; p.M=5120; p.N=512; p.K=512;
    launch_f<0,1,0,0>(p);
    float* HRl = (l==0)?HR0:HR1;
    rnnfuse_k<256><<<dim3(8,1,2),256,SMEM256>>>(
        XPH, sWhh + (size_t)l*2*256*256,
        sbih + (size_t)l*2*256, sbhh + (size_t)l*2*256, HRl, 256);
  }

  // object bidir RNN (hidden 512/dir)
  if (Ntot > 0) {
    int rb = (Ntot + 31)/32;
    for (int l=0;l<2;l++){
      GemmP p{}; p.A = (l==0)?ON:OR0; p.lda=1024;
      p.B = aWih + (size_t)l*2*512*1024; p.ldb=1024;
      p.C = XPO; p.ldc=1024; p.M=Ntot*20; p.N=1024; p.K=1024;
      launch_f<0,1,0,0>(p);
      float* ORl = (l==0)?OR0:OR1;
      rnnfuse_k<512><<<dim3(rb,1,2),256,SMEM512>>>(
          XPO, aWhh + (size_t)l*2*512*512,
          abih + (size_t)l*2*512, abhh + (size_t)l*2*512, ORl, Ntot);
    }
  }

  // heads
  { GemmP p{}; p.A=HR1; p.lda=512; p.B=chW1; p.ldb=512;
    p.C=A1H; p.ldc=512; p.M=5120; p.N=512; p.K=512;
    p.bias1=chb1; launch_f<0,1,0,1>(p); }
  head_k<<<256,256>>>(A1H, chW2, chb2, out, 10);

  if (Ntot > 0) {
    GemmP p{}; p.A=OR1; p.lda=1024; p.B=coW1; p.ldb=1024;
    p.C=A1O; p.ldc=512; p.M=Ntot*20; p.N=512; p.K=1024;
    p.bias1=cob1; launch_f<0,1,0,1>(p);
    head_k<<<Ntot,256>>>(A1O, coW2, cob2, out + 2560, 12);
  }
}

// round 8
// speedup vs baseline: 3.2400x; 1.3317x over previous
#include <cuda_runtime.h>
#include <cstdint>
#include <math.h>

// B=256 T=20 NOBJ=5 D=2048 P=1000 IN=2018 H=512

// ------------------------- device scratch -------------------------
__device__ float g_MH [2048*512];
__device__ float g_MO [2048*512];
__device__ float g_CHv[512];
__device__ float g_COv[512];
__device__ float g_Y  [30720*512];
__device__ float g_G1 [30720*512];
__device__ float g_Z  [30720*512];
__device__ float g_SG [30720*512];
__device__ float g_HN [5120*512];
__device__ float g_ON [25600*1024];
__device__ float g_XPH[5120*512];
__device__ float g_HR0[5120*512];
__device__ float g_HR1[5120*512];
__device__ float g_XPO[25600*1024];
__device__ float g_OR0[25600*1024];
__device__ float g_OR1[25600*1024];
__device__ float g_A1H[5120*512];
__device__ float g_A1O[25600*512];
__device__ int   g_off[257];

struct GemmP {
  const float* A; const float* B; float* C;
  int M, N, K;
  int lda, ldb, ldc;
  const float* bias1;
};

__device__ __forceinline__ float to_tf32(float x){
  float r; asm("cvt.rna.tf32.f32 %0, %1;" : "=f"(r) : "f"(x)); return r;
}

__device__ __forceinline__ void mma8(float (&c)[4], const float (&a)[4], const float (&b)[2]){
  asm volatile(
    "mma.sync.aligned.m16n8k8.row.col.f32.tf32.tf32.f32 "
    "{%0,%1,%2,%3}, {%4,%5,%6,%7}, {%8,%9}, {%0,%1,%2,%3};\n"
    : "+f"(c[0]), "+f"(c[1]), "+f"(c[2]), "+f"(c[3])
    : "r"(__float_as_uint(a[0])), "r"(__float_as_uint(a[1])),
      "r"(__float_as_uint(a[2])), "r"(__float_as_uint(a[3])),
      "r"(__float_as_uint(b[0])), "r"(__float_as_uint(b[1])));
}

__device__ __forceinline__ void cp16(float* smem_ptr, const float* gmem, bool pred){
  unsigned int s = (unsigned int)__cvta_generic_to_shared(smem_ptr);
  int sz = pred ? 16 : 0;
  asm volatile("cp.async.cg.shared.global [%0], [%1], 16, %2;\n"
               :: "r"(s), "l"(gmem), "r"(sz));
}
#define CP_COMMIT() asm volatile("cp.async.commit_group;\n")
#define CP_WAIT1()  asm volatile("cp.async.wait_group 1;\n")

// ---------------------------------------------------------------------------
// Double-buffered cp.async tf32 GEMM: BM=128, BN=128, BK=16; 8 warps (2m x 4n).
//  AMODE: 0 A[m*lda+k], 1 human-RF rows, 2 obj-RF rows, 3 A[k*lda+m]
//  BMODE: 0 B[k*ldb+n], 1 B[n*ldb+k]
//  CMODE: 0 crow=m, 1 crow=m*6, 2 obj row map
//  EPI:   0 none, 1 bias+relu
//  Tiles stored source-major; tf32 conversion happens on register frags.
//  Row-major tile: [128][20] (20%32 stride -> conflict-free frag reads).
//  K-major  tile:  [16][136] (136%32=8 -> conflict-free frag reads).
// ---------------------------------------------------------------------------
template<int AMODE,int BMODE,int CMODE,int EPI>
__global__ __launch_bounds__(256,2) void fgemm_k(GemmP p)
{
  constexpr bool AROW = (AMODE != 3);
  constexpr bool BROW = (BMODE == 1);
  constexpr int ASZ = AROW ? 128*20 : 16*136;
  constexpr int BSZ = BROW ? 128*20 : 16*136;
  __shared__ float As[2][ASZ];
  __shared__ float Bs[2][BSZ];

  const int m0 = blockIdx.y * 128;
  const int n0 = blockIdx.x * 128;
  const int tid = threadIdx.x, wid = tid>>5, lane = tid&31;
  const int gr = lane>>2, tg = lane&3;
  const int wm = (wid&1)*64, wn = (wid>>1)*32;

  float acc[4][4][4];
#pragma unroll
  for (int i=0;i<4;i++)
#pragma unroll
    for (int j=0;j<4;j++)
#pragma unroll
      for (int r=0;r<4;r++) acc[i][j][r]=0.f;

  auto loadA = [&](int kt, int st){
    int k0 = kt*16;
    if (AROW){
      for (int idx=tid; idx<512; idx+=256){
        int row=idx>>2, kq=idx&3; int m=m0+row, k=k0+kq*4;
        bool pred = (m < p.M) && (k+4 <= p.K);
        size_t base = 0;
        if (pred){
          if (AMODE==0) base = (size_t)m*p.lda;
          else if (AMODE==1){ int b=m/20, tt=m-b*20; base=((size_t)(b*120+tt))*2048; }
          else { int b=m/100, rm=m-b*100; int u=1+rm/20, tt=rm-(u-1)*20;
                 base=((size_t)(b*120+u*20+tt))*2048; }
        }
        cp16(&As[st][row*20+kq*4], pred ? (p.A+base+k) : p.A, pred);
      }
    } else {
      for (int idx=tid; idx<512; idx+=256){
        int kl=idx>>5, mq=idx&31; int k=k0+kl, m=m0+mq*4;
        bool pred = (k < p.K) && (m+4 <= p.M);
        cp16(&As[st][kl*136+mq*4], pred ? (p.A+(size_t)k*p.lda+m) : p.A, pred);
      }
    }
  };
  auto loadB = [&](int kt, int st){
    int k0 = kt*16;
    if (BROW){
      for (int idx=tid; idx<512; idx+=256){
        int row=idx>>2, kq=idx&3; int n=n0+row, k=k0+kq*4;
        bool pred = (n < p.N) && (k+4 <= p.K);
        cp16(&Bs[st][row*20+kq*4], pred ? (p.B+(size_t)n*p.ldb+k) : p.B, pred);
      }
    } else {
      for (int idx=tid; idx<512; idx+=256){
        int kl=idx>>5, nq=idx&31; int k=k0+kl, n=n0+nq*4;
        bool pred = (k < p.K) && (n+4 <= p.N);
        cp16(&Bs[st][kl*136+nq*4], pred ? (p.B+(size_t)k*p.ldb+n) : p.B, pred);
      }
    }
  };

  const int ntk = (p.K + 15) >> 4;
  loadA(0,0); loadB(0,0);
  CP_COMMIT();

  for (int kt=0; kt<ntk; kt++){
    int st = kt & 1;
    if (kt+1 < ntk){ loadA(kt+1, st^1); loadB(kt+1, st^1); }
    CP_COMMIT();
    CP_WAIT1();
    __syncthreads();

#pragma unroll
    for (int kk=0; kk<16; kk+=8){
      float a[4][4];
#pragma unroll
      for (int i=0;i<4;i++){
        int mr = wm + i*16 + gr;
        if (AROW){
          a[i][0]=to_tf32(As[st][ mr   *20 + kk+tg  ]);
          a[i][1]=to_tf32(As[st][(mr+8)*20 + kk+tg  ]);
          a[i][2]=to_tf32(As[st][ mr   *20 + kk+tg+4]);
          a[i][3]=to_tf32(As[st][(mr+8)*20 + kk+tg+4]);
        } else {
          a[i][0]=to_tf32(As[st][(kk+tg  )*136 + mr  ]);
          a[i][1]=to_tf32(As[st][(kk+tg  )*136 + mr+8]);
          a[i][2]=to_tf32(As[st][(kk+tg+4)*136 + mr  ]);
          a[i][3]=to_tf32(As[st][(kk+tg+4)*136 + mr+8]);
        }
      }
      float b[4][2];
#pragma unroll
      for (int j=0;j<4;j++){
        int nc = wn + j*8 + gr;
        if (BROW){
          b[j][0]=to_tf32(Bs[st][nc*20 + kk+tg  ]);
          b[j][1]=to_tf32(Bs[st][nc*20 + kk+tg+4]);
        } else {
          b[j][0]=to_tf32(Bs[st][(kk+tg  )*136 + nc]);
          b[j][1]=to_tf32(Bs[st][(kk+tg+4)*136 + nc]);
        }
      }
#pragma unroll
      for (int i=0;i<4;i++)
#pragma unroll
        for (int j=0;j<4;j++) mma8(acc[i][j], a[i], b[j]);
    }
    __syncthreads();
  }

  // ---- epilogue
#pragma unroll
  for (int i=0;i<4;i++){
#pragma unroll
    for (int r=0;r<4;r++){
      int m = m0 + wm + i*16 + gr + ((r>=2)?8:0);
      if (m >= p.M) continue;
      size_t crow;
      if (CMODE==0) crow = (size_t)m;
      else if (CMODE==1) crow = (size_t)m * 6;
      else { int b=m/100, rm=m-b*100; int u=1+rm/20, tt=rm-(u-1)*20;
             crow = ((size_t)(b*20+tt))*6 + u; }
#pragma unroll
      for (int j=0;j<4;j++){
        int n = n0 + wn + j*8 + tg*2 + (r&1);
        if (n >= p.N) continue;
        float v = acc[i][j][r];
        if (EPI==1){ v += p.bias1[n]; v = fmaxf(v, 0.f); }
        p.C[crow*(size_t)p.ldc + n] = v;
      }
    }
  }
}

// ---------------------------------------------------------------------------
// Persistent fused bidir RNN layer: block owns 32 rows, loops 20 steps.
// ---------------------------------------------------------------------------
template<int HD>
__global__ __launch_bounds__(256) void rnnfuse_k(const float* __restrict__ XP,
    const float* __restrict__ Whh, const float* __restrict__ bih,
    const float* __restrict__ bhh, float* __restrict__ OUT, int M)
{
  constexpr int HP = HD+4;
  constexpr int BP = HD+8;
  constexpr int NJ = HD/64;
  extern __shared__ float sm[];
  float* hs  = sm;
  float* Bsm = sm + 32*HP;

  const int d  = blockIdx.z;
  const int r0 = blockIdx.x*32;
  const int tid = threadIdx.x, wid = tid>>5, lane = tid&31;
  const int gr = lane>>2, tg = lane&3;
  const int wn = wid*(HD/8);
  const float* Bp = Whh + (size_t)d*HD*HD;

  float bb[NJ][2];
#pragma unroll
  for (int j=0;j<NJ;j++){
    int n = wn + j*8 + tg*2;
    bb[j][0] = bih[d*HD+n]   + bhh[d*HD+n];
    bb[j][1] = bih[d*HD+n+1] + bhh[d*HD+n+1];
  }

  for (int s=0; s<20; s++){
    int t = d ? (19 - s) : s;
    float acc[2][NJ][4];
#pragma unroll
    for (int i=0;i<2;i++)
#pragma unroll
      for (int j=0;j<NJ;j++)
#pragma unroll
        for (int r=0;r<4;r++) acc[i][j][r]=0.f;

    if (s > 0){
      for (int k0=0; k0<HD; k0+=16){
        __syncthreads();
        for (int idx=tid; idx<HD*4; idx+=256){
          int nl=idx>>2, kq=idx&3;
          float4 v = *(const float4*)&Bp[(size_t)nl*HD + k0 + kq*4];
          Bsm[(kq*4+0)*BP + nl]=to_tf32(v.x);
          Bsm[(kq*4+1)*BP + nl]=to_tf32(v.y);
          Bsm[(kq*4+2)*BP + nl]=to_tf32(v.z);
          Bsm[(kq*4+3)*BP + nl]=to_tf32(v.w);
        }
        __syncthreads();
#pragma unroll
        for (int kk=0; kk<16; kk+=8){
          float a[2][4];
#pragma unroll
          for (int i=0;i<2;i++){
            int lr = i*16 + gr;
            a[i][0]=hs[ lr   *HP + k0+kk+tg  ];
            a[i][1]=hs[(lr+8)*HP + k0+kk+tg  ];
            a[i][2]=hs[ lr   *HP + k0+kk+tg+4];
            a[i][3]=hs[(lr+8)*HP + k0+kk+tg+4];
          }
          float b[NJ][2];
#pragma unroll
          for (int j=0;j<NJ;j++){
            int nc = wn + j*8 + gr;
            b[j][0]=Bsm[(kk+tg  )*BP + nc];
            b[j][1]=Bsm[(kk+tg+4)*BP + nc];
          }
#pragma unroll
          for (int i=0;i<2;i++)
#pragma unroll
            for (int j=0;j<NJ;j++) mma8(acc[i][j], a[i], b[j]);
        }
      }
    }
    __syncthreads();
#pragma unroll
    for (int i=0;i<2;i++)
#pragma unroll
      for (int r=0;r<4;r++){
        int lm = i*16 + gr + ((r>=2)?8:0);
        int m  = r0 + lm;
#pragma unroll
        for (int j=0;j<NJ;j++){
          int n = wn + j*8 + tg*2 + (r&1);
          if (m < M){
            size_t o = ((size_t)m*20 + t)*(size_t)(2*HD) + (size_t)d*HD + n;
            float v = tanhf(acc[i][j][r] + XP[o] + bb[j][r&1]);
            OUT[o] = v;
            hs[lm*HP + n] = to_tf32(v);
          } else {
            hs[lm*HP + n] = 0.f;
          }
        }
      }
  }
}

__global__ void chco_k(const float* bph, const float* bpo, const float* Wg1,
                       float* CHv, float* COv)
{
  __shared__ float sa[256], sc[256];
  int hl = threadIdx.x & 31, sl = threadIdx.x >> 5;
  int h = blockIdx.x*32 + hl;
  float a=0.f, c=0.f;
  for (int q=0; q<125; q++){
    int pp = sl*125 + q;
    a += bph[pp]*Wg1[(size_t)(4+pp)*512 + h];
    c += bpo[pp]*Wg1[(size_t)(1004+pp)*512 + h];
  }
  sa[threadIdx.x]=a; sc[threadIdx.x]=c;
  __syncthreads();
  if (sl==0){
    for (int s2=1;s2<8;s2++){ a+=sa[s2*32+hl]; c+=sc[s2*32+hl]; }
    CHv[h]=a; COv[h]=c;
  }
}

__global__ void mix1_k(const float* __restrict__ Y, const float* __restrict__ Wg1,
                       const float* __restrict__ bg1, const float* __restrict__ bbox,
                       const float* __restrict__ oh, const float* __restrict__ CHv,
                       const float* __restrict__ COv, float* __restrict__ G1)
{
  int bt = blockIdx.x; int b = bt/20, t = bt - b*20;
  __shared__ float sb[24], so[50];
  int tid = threadIdx.x;
  if (tid < 24) sb[tid] = bbox[((size_t)(b*6 + (tid>>2))*20 + t)*4 + (tid&3)];
  if (tid >= 32 && tid < 82) {
    int q = tid-32;
    so[q] = oh[((size_t)(b*5 + q/10)*20 + t)*10 + (q - (q/10)*10)];
  }
  __syncthreads();
  int h = tid;
  size_t base = (size_t)bt * 6 * 512;
  float y0 = Y[base + h] + CHv[h];
#pragma unroll
  for (int i=0;i<4;i++) y0 += sb[i]*Wg1[(size_t)i*512 + h];
  float ys = 0.f, yu[5];
#pragma unroll
  for (int u=1; u<=5; u++){
    float v = Y[base + (size_t)u*512 + h] + COv[h];
#pragma unroll
    for (int i=0;i<4;i++) v += sb[u*4+i]*Wg1[(size_t)(2004+i)*512 + h];
#pragma unroll
    for (int j=0;j<10;j++) v += so[(u-1)*10+j]*Wg1[(size_t)(2008+j)*512 + h];
    yu[u-1]=v; ys += v;
  }
  const float R6 = 1.f/6.f, R12 = 0.28867513459481287f;
  float bg = bg1[h];
  G1[base + h] = fmaxf(R6*y0 + R12*ys + bg, 0.f);
#pragma unroll
  for (int u=1;u<=5;u++)
    G1[base + (size_t)u*512 + h] = fmaxf(R12*y0 + 0.5f*yu[u-1] + bg, 0.f);
}

__global__ void mix2_k(const float* __restrict__ Z, const float* __restrict__ bg2,
                       float* __restrict__ SG, float* __restrict__ HN)
{
  int bt = blockIdx.x;
  int h = threadIdx.x;
  size_t base = (size_t)bt*6*512;
  float z0 = Z[base+h];
  float zs=0.f, zu[5];
#pragma unroll
  for (int u=1;u<=5;u++){ float v = Z[base+(size_t)u*512+h]; zu[u-1]=v; zs+=v; }
  const float R6 = 1.f/6.f, R12 = 0.28867513459481287f;
  float bg = bg2[h];
  float g0 = fmaxf(R6*z0 + R12*zs + bg, 0.f);
  SG[base+h]=g0;
  HN[(size_t)bt*512+h]=g0;
#pragma unroll
  for (int u=1;u<=5;u++)
    SG[base+(size_t)u*512+h] = fmaxf(R12*z0 + 0.5f*zu[u-1] + bg, 0.f);
}

__global__ void prefix_k(const int* num, int* off){
  if (threadIdx.x==0){
    int a=0;
    for (int b=0;b<256;b++){ off[b]=a; a+=num[b]; }
    off[256]=a;
  }
}

__global__ void gather_k(const float* __restrict__ SG, const int* __restrict__ num,
                         const int* __restrict__ off, float* __restrict__ ON)
{
  int bk = blockIdx.x; int b = bk/5, k = bk - b*5;
  if (k >= num[b]) return;
  int t = blockIdx.y;
  int r = off[b] + k;
  size_t ob  = ((size_t)r*20 + t)*1024;
  size_t sgb = ((size_t)(b*20+t))*6*512;
  int h = threadIdx.x;
  ON[ob + h]       = SG[sgb + h];
  ON[ob + 512 + h] = SG[sgb + (size_t)(k+1)*512 + h];
}

__global__ void head_k(const float* __restrict__ A1, const float* __restrict__ W2,
                       const float* __restrict__ b2, float* __restrict__ out, int nout)
{
  int r = blockIdx.x;
  __shared__ float cs[512];
  __shared__ float red[256];
  int tid = threadIdx.x;
  for (int j = tid; j < 512; j += 256){
    float s = 0.f;
    for (int t=0;t<20;t++) s += A1[((size_t)r*20 + t)*512 + j];
    cs[j] = s;
  }
  __syncthreads();
  for (int i=0;i<nout;i++){
    float v = cs[tid]*W2[(size_t)i*512+tid] + cs[tid+256]*W2[(size_t)i*512+tid+256];
    red[tid]=v; __syncthreads();
    for (int st=128; st>0; st>>=1){ if (tid<st) red[tid]+=red[tid+st]; __syncthreads(); }
    if (tid==0) out[(size_t)r*nout + i] = red[0] + 20.f*b2[i];
    __syncthreads();
  }
}

// ------------------------------- host side ---------------------------------
template<int AM,int BM2,int CM,int EP>
static inline void launch_f(const GemmP& p){
  dim3 g((unsigned)((p.N+127)/128), (unsigned)((p.M+127)/128), 1);
  fgemm_k<AM,BM2,CM,EP><<<g,256>>>(p);
}

extern "C" void kernel_launch(void* const* d_in, const int* in_sizes, int n_in,
                              void* d_out, int out_size)
{
  const float* one_hot = (const float*)d_in[0];
  const float* bbox    = (const float*)d_in[1];
  const int*   numobj  = (const int*)  d_in[2];
  const float* rf      = (const float*)d_in[3];
  const float* Wph  = (const float*)d_in[4];
  const float* bph  = (const float*)d_in[5];
  const float* Wpo  = (const float*)d_in[6];
  const float* bpo  = (const float*)d_in[7];
  const float* Wg1  = (const float*)d_in[8];
  const float* bg1  = (const float*)d_in[9];
  const float* Wg2  = (const float*)d_in[10];
  const float* bg2  = (const float*)d_in[11];
  const float* sWih = (const float*)d_in[12];
  const float* sWhh = (const float*)d_in[13];
  const float* sbih = (const float*)d_in[14];
  const float* sbhh = (const float*)d_in[15];
  const float* aWih = (const float*)d_in[16];
  const float* aWhh = (const float*)d_in[17];
  const float* abih = (const float*)d_in[18];
  const float* abhh = (const float*)d_in[19];
  const float* chW1 = (const float*)d_in[20];
  const float* chb1 = (const float*)d_in[21];
  const float* chW2 = (const float*)d_in[22];
  const float* chb2 = (const float*)d_in[23];
  const float* coW1 = (const float*)d_in[24];
  const float* cob1 = (const float*)d_in[25];
  const float* coW2 = (const float*)d_in[26];
  const float* cob2 = (const float*)d_in[27];
  float* out = (float*)d_out;

  int Ntot = (out_size - 2560) / 12;
  if (Ntot < 0) Ntot = 0; if (Ntot > 1280) Ntot = 1280;

  float *MH,*MO,*CHv,*COv,*Y,*G1,*Z,*SG,*HN,*ON,*XPH,*HR0,*HR1,*XPO,*OR0,*OR1,*A1H,*A1O;
  int *off;
  cudaGetSymbolAddress((void**)&MH,  g_MH);
  cudaGetSymbolAddress((void**)&MO,  g_MO);
  cudaGetSymbolAddress((void**)&CHv, g_CHv);
  cudaGetSymbolAddress((void**)&COv, g_COv);
  cudaGetSymbolAddress((void**)&Y,   g_Y);
  cudaGetSymbolAddress((void**)&G1,  g_G1);
  cudaGetSymbolAddress((void**)&Z,   g_Z);
  cudaGetSymbolAddress((void**)&SG,  g_SG);
  cudaGetSymbolAddress((void**)&HN,  g_HN);
  cudaGetSymbolAddress((void**)&ON,  g_ON);
  cudaGetSymbolAddress((void**)&XPH, g_XPH);
  cudaGetSymbolAddress((void**)&HR0, g_HR0);
  cudaGetSymbolAddress((void**)&HR1, g_HR1);
  cudaGetSymbolAddress((void**)&XPO, g_XPO);
  cudaGetSymbolAddress((void**)&OR0, g_OR0);
  cudaGetSymbolAddress((void**)&OR1, g_OR1);
  cudaGetSymbolAddress((void**)&A1H, g_A1H);
  cudaGetSymbolAddress((void**)&A1O, g_A1O);
  cudaGetSymbolAddress((void**)&off, g_off);

  const int SMEM512 = 32*(512+4)*4 + 16*(512+8)*4;  // 99,328 B
  const int SMEM256 = 32*(256+4)*4 + 16*(256+8)*4;  // 50,176 B
  cudaFuncSetAttribute(rnnfuse_k<512>, cudaFuncAttributeMaxDynamicSharedMemorySize, SMEM512);
  cudaFuncSetAttribute(rnnfuse_k<256>, cudaFuncAttributeMaxDynamicSharedMemorySize, SMEM256);

  // MH = Wph^T @ Wg1[4:1004] ; MO = Wpo^T @ Wg1[1004:2004]
  { GemmP p{}; p.A=Wph; p.lda=2048; p.B=Wg1+4*512; p.ldb=512;
    p.C=MH; p.ldc=512; p.M=2048; p.N=512; p.K=1000; launch_f<3,0,0,0>(p); }
  { GemmP p{}; p.A=Wpo; p.lda=2048; p.B=Wg1+1004*512; p.ldb=512;
    p.C=MO; p.ldc=512; p.M=2048; p.N=512; p.K=1000; launch_f<3,0,0,0>(p); }
  chco_k<<<16,256>>>(bph, bpo, Wg1, CHv, COv);

  // Y = rf @ M  (written [b,t,u,512])
  { GemmP p{}; p.A=rf; p.B=MH; p.ldb=512;
    p.C=Y; p.ldc=512; p.M=5120; p.N=512; p.K=2048; launch_f<1,0,1,0>(p); }
  { GemmP p{}; p.A=rf; p.B=MO; p.ldb=512;
    p.C=Y; p.ldc=512; p.M=25600; p.N=512; p.K=2048; launch_f<2,0,2,0>(p); }
  mix1_k<<<5120,512>>>(Y, Wg1, bg1, bbox, one_hot, CHv, COv, G1);

  // Z = G1 @ Wg2 -> mix2 -> SG, HN
  { GemmP p{}; p.A=G1; p.lda=512; p.B=Wg2; p.ldb=512;
    p.C=Z; p.ldc=512; p.M=30720; p.N=512; p.K=512; launch_f<0,0,0,0>(p); }
  mix2_k<<<5120,512>>>(Z, bg2, SG, HN);

  prefix_k<<<1,32>>>(numobj, off);
  gather_k<<<dim3(1280,20),512>>>(SG, numobj, off, ON);

  // human bidir RNN (hidden 256/dir)
  for (int l=0;l<2;l++){
    GemmP p{}; p.A = (l==0)?HN:HR0; p.lda=512;
    p.B = sWih + (size_t)l*2*256*512; p.ldb=512;
    p.C = XPH; p.ldc=512; p.M=5120; p.N=512; p.K=512;
    launch_f<0,1,0,0>(p);
    float* HRl = (l==0)?HR0:HR1;
    rnnfuse_k<256><<<dim3(8,1,2),256,SMEM256>>>(
        XPH, sWhh + (size_t)l*2*256*256,
        sbih + (size_t)l*2*256, sbhh + (size_t)l*2*256, HRl, 256);
  }

  // object bidir RNN (hidden 512/dir)
  if (Ntot > 0) {
    int rb = (Ntot + 31)/32;
    for (int l=0;l<2;l++){
      GemmP p{}; p.A = (l==0)?ON:OR0; p.lda=1024;
      p.B = aWih + (size_t)l*2*512*1024; p.ldb=1024;
      p.C = XPO; p.ldc=1024; p.M=Ntot*20; p.N=1024; p.K=1024;
      launch_f<0,1,0,0>(p);
      float* ORl = (l==0)?OR0:OR1;
      rnnfuse_k<512><<<dim3(rb,1,2),256,SMEM512>>>(
          XPO, aWhh + (size_t)l*2*512*512,
          abih + (size_t)l*2*512, abhh + (size_t)l*2*512, ORl, Ntot);
    }
  }

  // heads
  { GemmP p{}; p.A=HR1; p.lda=512; p.B=chW1; p.ldb=512;
    p.C=A1H; p.ldc=512; p.M=5120; p.N=512; p.K=512;
    p.bias1=chb1; launch_f<0,1,0,1>(p); }
  head_k<<<256,256>>>(A1H, chW2, chb2, out, 10);

  if (Ntot > 0) {
    GemmP p{}; p.A=OR1; p.lda=1024; p.B=coW1; p.ldb=1024;
    p.C=A1O; p.ldc=512; p.M=Ntot*20; p.N=512; p.K=1024;
    p.bias1=cob1; launch_f<0,1,0,1>(p);
    head_k<<<Ntot,256>>>(A1O, coW2, cob2, out + 2560, 12);
  }
}